// round 8
// baseline (speedup 1.0000x reference)
#include <cuda_runtime.h>

// Problem constants (fixed by the dataset): B=512, T=512, L=128
#define BB 512
#define TT 512
#define LL 128
#define NB 2                 // batches per CTA
#define NCTA (BB / NB)       // 256 CTAs, 2 co-resident per SM
#define PROW 136             // padded P row (floats): cols 0-63 at [0,64), 64-127 at [68,132)
#define LN2F 0.69314718f

__device__ __forceinline__ unsigned long long pack2(float x, float y) {
    unsigned long long r;
    asm("mov.b64 %0, {%1, %2};" : "=l"(r) : "f"(x), "f"(y));
    return r;
}
__device__ __forceinline__ void unpack2(float& x, float& y, unsigned long long v) {
    asm("mov.b64 {%0, %1}, %2;" : "=f"(x), "=f"(y) : "l"(v));
}
// Packed f32x2 FMA — 2x fp32 throughput on sm_103a.
__device__ __forceinline__ unsigned long long fma2(unsigned long long a,
                                                   unsigned long long b,
                                                   unsigned long long c) {
    unsigned long long d;
    asm("fma.rn.f32x2 %0, %1, %2, %3;" : "=l"(d) : "l"(a), "l"(b), "l"(c));
    return d;
}
__device__ __forceinline__ unsigned long long add2(unsigned long long a,
                                                   unsigned long long b) {
    unsigned long long d;
    asm("add.rn.f32x2 %0, %1, %2;" : "=l"(d) : "l"(a), "l"(b));
    return d;
}
__device__ __forceinline__ float hsum2(unsigned long long v) {
    float x, y;
    unpack2(x, y, v);
    return x + y;
}

// Persistent: one CTA = NB=2 batches, 2 CTAs/SM (independent barrier domains).
// 128 threads. Thread (warp w, lane l):
//   jj  = w*16 + (l & 15) : base column in [0,64);  ih = l>>4 : i-half
//   owns columns jj and jj+64 (E regs 2 x 32 f32x2); recurrence col = jj+64*ih.
// LINEAR-DOMAIN recurrence: W = exp(prev - kacc*ln2). Per step the critical
// chain is FMUL -> STS -> BAR -> LDS -> FMA -> shfl -> FMUL; all MUFU work
// (exp of features) runs 1-2 steps early, and the power-of-two rescale comes
// from the smem-broadcast anchor P[0] via exact integer exponent arithmetic.
__global__ __launch_bounds__(128, 2) void crf_kernel(
    const float* __restrict__ feats,     // [B, T, L]
    const float* __restrict__ transfer,  // [L, L]
    const int*   __restrict__ target,    // [B, T]
    const int*   __restrict__ startp,    // scalar (may be null -> L-2)
    const int*   __restrict__ stopp,     // scalar (may be null -> L-1)
    float*       __restrict__ out)       // [B]
{
    __shared__ __align__(16) float Psh[2][NB][PROW];  // double-buffered padded P
    __shared__ float smax[NB][4];
    __shared__ float ssum[NB][4];
    __shared__ float sg[NB][4];

    const int tid  = threadIdx.x;
    const int lane = tid & 31;
    const int wid  = tid >> 5;
    const int jj   = (wid << 4) + (lane & 15);
    const int ih   = lane >> 4;                 // i-half
    const int jown = jj + (ih << 6);            // recurrence column owned
    const int fown = jj + ih * 68;              // padded float offset of jown
    const int b0   = blockIdx.x * NB;

    const int start = startp ? *startp : (LL - 2);
    const int stop  = stopp  ? *stopp  : (LL - 1);

    // ---- E tiles: i in [64*ih, 64*ih+64) for columns j0=jj and j1=jj+64 ----
    unsigned long long Ea[32], Eb[32];   // Ea: column jj, Eb: column jj+64
    {
        const int i0 = ih << 6;
#pragma unroll
        for (int m = 0; m < 32; m++) {
            const int ia = i0 + 2 * m;
            Ea[m] = pack2(__expf(transfer[ia * LL + jj]),
                          __expf(transfer[(ia + 1) * LL + jj]));
            Eb[m] = pack2(__expf(transfer[ia * LL + jj + 64]),
                          __expf(transfer[(ia + 1) * LL + jj + 64]));
        }
    }

    const float* fb[NB];
    const int*   tb[NB];
#pragma unroll
    for (int nb = 0; nb < NB; nb++) {
        fb[nb] = feats  + (size_t)(b0 + nb) * TT * LL;
        tb[nb] = target + (size_t)(b0 + nb) * TT;
    }

    // ---- Gold-path partial sums (emit + trans), strided over t ----
    float g[NB];
#pragma unroll
    for (int nb = 0; nb < NB; nb++) {
        float acc = 0.f;
        for (int t = 1 + tid; t < TT; t += 128) {
            const int tg = tb[nb][t];
            const int pr = (t == 1) ? start : tb[nb][t - 1];
            acc += fb[nb][t * LL + tg] + transfer[pr * LL + tg];
        }
        g[nb] = acc;
    }

    // ---- Recurrence state (linear domain) ----
    // W = exp(prev - kacc*ln2); EF pipeline: efcur for this step, efnext for
    // the next, fraw just-loaded (exp'd one step before use).
    float W[NB], efcur[NB], efnext[NB], fraw[NB];
    int   kacc[NB];
    {
        const float tstart = transfer[start * LL + jown];
#pragma unroll
        for (int nb = 0; nb < NB; nb++) {
            W[nb]      = __expf(fb[nb][1 * LL + jown] + tstart);  // prev0, A=0
            efcur[nb]  = __expf(fb[nb][2 * LL + jown]);
            efnext[nb] = __expf(fb[nb][3 * LL + jown]);
            fraw[nb]   = fb[nb][4 * LL + jown];
            kacc[nb]   = 0;
        }
    }

    // LDS base (in ulonglong2) of this thread's i-half within a P row
    const int pbase = ih * 17;

    // ---- Main scan: t = 2 .. T-1 ----
    for (int t = 2; t < TT; t++) {
        const int tn = (t + 3 < TT) ? (t + 3) : (TT - 1);
        const int buf = t & 1;
        float fnew[NB];
#pragma unroll
        for (int nb = 0; nb < NB; nb++) {
            fnew[nb] = fb[nb][tn * LL + jown];          // prefetch 3 ahead
            Psh[buf][nb][fown] = W[nb] * efcur[nb];     // P = exp(prev + f - A)
        }
        __syncthreads();

        // Anchors: broadcast read of P[0] per batch (ALU-only scale derivation,
        // runs in parallel with the dot).
        const float anc0 = Psh[buf][0][0];
        const float anc1 = Psh[buf][1][0];

        // Partial dots over own i-half for both columns, both batches.
        const ulonglong2* P0 =
            reinterpret_cast<const ulonglong2*>(Psh[buf][0]) + pbase;
        const ulonglong2* P1 =
            reinterpret_cast<const ulonglong2*>(Psh[buf][1]) + pbase;
        unsigned long long aA0 = 0ull, bA0 = 0ull, aB0 = 0ull, bB0 = 0ull;
        unsigned long long aA1 = 0ull, bA1 = 0ull, aB1 = 0ull, bB1 = 0ull;
#pragma unroll
        for (int k = 0; k < 16; k++) {
            const unsigned long long ea0 = Ea[2 * k];
            const unsigned long long ea1 = Ea[2 * k + 1];
            const unsigned long long eb0 = Eb[2 * k];
            const unsigned long long eb1 = Eb[2 * k + 1];
            const ulonglong2 q0 = P0[k];
            aA0 = fma2(q0.x, ea0, aA0);
            bA0 = fma2(q0.y, ea1, bA0);
            aB0 = fma2(q0.x, eb0, aB0);
            bB0 = fma2(q0.y, eb1, bB0);
            const ulonglong2 q1 = P1[k];
            aA1 = fma2(q1.x, ea0, aA1);
            bA1 = fma2(q1.y, ea1, bA1);
            aB1 = fma2(q1.x, eb0, aB1);
            bB1 = fma2(q1.y, eb1, bB1);
        }
        float sA0 = hsum2(add2(aA0, bA0));
        float sB0 = hsum2(add2(aB0, bB0));
        float sA1 = hsum2(add2(aA1, bA1));
        float sB1 = hsum2(add2(aB1, bB1));
        sA0 += __shfl_xor_sync(0xffffffffu, sA0, 16);
        sB0 += __shfl_xor_sync(0xffffffffu, sB0, 16);
        sA1 += __shfl_xor_sync(0xffffffffu, sA1, 16);
        sB1 += __shfl_xor_sync(0xffffffffu, sB1, 16);

        const float s0 = ih ? sB0 : sA0;   // full dot for owned column, batch 0
        const float s1 = ih ? sB1 : sA1;   // batch 1

        // Exact power-of-two rescale: k = ilogb(anchor)+7, W = S * 2^-k.
        const int e0 = (__float_as_int(anc0) >> 23) & 255;
        const int e1 = (__float_as_int(anc1) >> 23) & 255;
        const float sc0 = __int_as_float((247 - e0) << 23);
        const float sc1 = __int_as_float((247 - e1) << 23);
        kacc[0] += e0 - 120;               // (e0-127) + 7
        kacc[1] += e1 - 120;

        W[0] = s0 * sc0;
        W[1] = s1 * sc1;

        // rotate the exp(f) pipeline (MUFU off the critical path)
#pragma unroll
        for (int nb = 0; nb < NB; nb++) {
            efcur[nb]  = efnext[nb];
            efnext[nb] = __expf(fraw[nb]);
            fraw[nb]   = fnew[nb];
        }
    }

    // ---- Reconstruct prev_j once, then epilogue as before ----
    float prev[NB];
#pragma unroll
    for (int nb = 0; nb < NB; nb++)
        prev[nb] = __logf(W[nb]) + (float)kacc[nb] * LN2F;

    const float tstop = transfer[jown * LL + stop];
#pragma unroll
    for (int nb = 0; nb < NB; nb++) {
        const float vv = prev[nb] + tstop;
        float m = vv;
#pragma unroll
        for (int off = 16; off; off >>= 1)
            m = fmaxf(m, __shfl_xor_sync(0xffffffffu, m, off));
        if (lane == 0) smax[nb][wid] = m;
    }
    __syncthreads();
#pragma unroll
    for (int nb = 0; nb < NB; nb++) {
        const float mm = fmaxf(fmaxf(smax[nb][0], smax[nb][1]),
                               fmaxf(smax[nb][2], smax[nb][3]));
        float es = __expf((prev[nb] + tstop) - mm);
        float gg = g[nb];
#pragma unroll
        for (int off = 16; off; off >>= 1) {
            es += __shfl_xor_sync(0xffffffffu, es, off);
            gg += __shfl_xor_sync(0xffffffffu, gg, off);
        }
        if (lane == 0) { ssum[nb][wid] = es; sg[nb][wid] = gg; }
    }
    __syncthreads();

    if (tid < NB) {
        const int nb = tid;
        const float mm = fmaxf(fmaxf(smax[nb][0], smax[nb][1]),
                               fmaxf(smax[nb][2], smax[nb][3]));
        const float Ssum = ssum[nb][0] + ssum[nb][1] + ssum[nb][2] + ssum[nb][3];
        const float sentence = mm + __logf(Ssum);
        const float gsum = sg[nb][0] + sg[nb][1] + sg[nb][2] + sg[nb][3];
        const float emit0 = fb[nb][start];  // feats[b, 0, start]
        out[b0 + nb] = sentence - __expf(emit0 + gsum);
    }
}

extern "C" void kernel_launch(void* const* d_in, const int* in_sizes, int n_in,
                              void* d_out, int out_size) {
    const float* feats    = (const float*)d_in[0];
    const float* transfer = (const float*)d_in[1];
    const int*   target   = (const int*)d_in[2];
    const int*   startp   = (n_in >= 4) ? (const int*)d_in[3] : nullptr;
    const int*   stopp    = (n_in >= 5) ? (const int*)d_in[4] : nullptr;

    crf_kernel<<<NCTA, 128>>>(feats, transfer, target, startp, stopp, (float*)d_out);
}

// round 9
// speedup vs baseline: 1.0071x; 1.0071x over previous
#include <cuda_runtime.h>

// Problem constants (fixed by the dataset): B=512, T=512, L=128
#define BB 512
#define TT 512
#define LL 128
#define NB 2                 // batches per CTA
#define NCTA (BB / NB)       // 256 CTAs, 2 co-resident per SM
#define PROW 136             // padded P row (floats): cols 0-63 at [0,64), 64-127 at [68,132)
#define C128 0.0078125f      // 2^-7 : exact per-step rescale (ln128 == 7*ln2)
#define KFINAL 2474.5354346f // 510 steps * 7 * ln2  (total rescale to add back)

__device__ __forceinline__ unsigned long long pack2(float x, float y) {
    unsigned long long r;
    asm("mov.b64 %0, {%1, %2};" : "=l"(r) : "f"(x), "f"(y));
    return r;
}
__device__ __forceinline__ void unpack2(float& x, float& y, unsigned long long v) {
    asm("mov.b64 {%0, %1}, %2;" : "=f"(x), "=f"(y) : "l"(v));
}
// Packed f32x2 FMA — 2x fp32 throughput on sm_103a.
__device__ __forceinline__ unsigned long long fma2(unsigned long long a,
                                                   unsigned long long b,
                                                   unsigned long long c) {
    unsigned long long d;
    asm("fma.rn.f32x2 %0, %1, %2, %3;" : "=l"(d) : "l"(a), "l"(b), "l"(c));
    return d;
}
__device__ __forceinline__ unsigned long long add2(unsigned long long a,
                                                   unsigned long long b) {
    unsigned long long d;
    asm("add.rn.f32x2 %0, %1, %2;" : "=l"(d) : "l"(a), "l"(b));
    return d;
}
__device__ __forceinline__ float hsum2(unsigned long long v) {
    float x, y;
    unpack2(x, y, v);
    return x + y;
}

// Persistent: one CTA = NB=2 batches, 2 CTAs/SM (independent barrier domains).
// 128 threads. Thread (warp w, lane l):
//   jj = w*16 + (l & 15) : base column in [0,64);  ih = l>>4 : i-half
//   owns columns jj and jj+64 (E regs 2 x 32 f32x2); recurrence col = jj+64*ih.
// LINEAR-DOMAIN recurrence with CONSTANT rescale: W = exp(prev - 7*ln2*steps).
// Since ln(128) = 7*ln2 exactly, a fixed 2^-7 per step (folded into the
// precomputed exp(f) factor) keeps W bounded with no anchor, no feedback,
// no log/exp on the critical path. Chain per step:
//   BAR -> LDS -> FMA chain -> shfl -> FMUL -> STS -> BAR.
__global__ __launch_bounds__(128, 2) void crf_kernel(
    const float* __restrict__ feats,     // [B, T, L]
    const float* __restrict__ transfer,  // [L, L]
    const int*   __restrict__ target,    // [B, T]
    const int*   __restrict__ startp,    // scalar (may be null -> L-2)
    const int*   __restrict__ stopp,     // scalar (may be null -> L-1)
    float*       __restrict__ out)       // [B]
{
    __shared__ __align__(16) float Psh[2][NB][PROW];  // double-buffered padded P
    __shared__ float smax[NB][4];
    __shared__ float ssum[NB][4];
    __shared__ float sg[NB][4];

    const int tid  = threadIdx.x;
    const int lane = tid & 31;
    const int wid  = tid >> 5;
    const int jj   = (wid << 4) + (lane & 15);
    const int ih   = lane >> 4;                 // i-half
    const int jown = jj + (ih << 6);            // recurrence column owned
    const int fown = jj + ih * 68;              // padded float offset of jown
    const int b0   = blockIdx.x * NB;

    const int start = startp ? *startp : (LL - 2);
    const int stop  = stopp  ? *stopp  : (LL - 1);

    // ---- E tiles: i in [64*ih, 64*ih+64) for columns j0=jj and j1=jj+64 ----
    unsigned long long Ea[32], Eb[32];   // Ea: column jj, Eb: column jj+64
    {
        const int i0 = ih << 6;
#pragma unroll
        for (int m = 0; m < 32; m++) {
            const int ia = i0 + 2 * m;
            Ea[m] = pack2(__expf(transfer[ia * LL + jj]),
                          __expf(transfer[(ia + 1) * LL + jj]));
            Eb[m] = pack2(__expf(transfer[ia * LL + jj + 64]),
                          __expf(transfer[(ia + 1) * LL + jj + 64]));
        }
    }

    const float* fb[NB];
    const int*   tb[NB];
#pragma unroll
    for (int nb = 0; nb < NB; nb++) {
        fb[nb] = feats  + (size_t)(b0 + nb) * TT * LL;
        tb[nb] = target + (size_t)(b0 + nb) * TT;
    }

    // ---- Gold-path partial sums (emit + trans), strided over t ----
    float g[NB];
#pragma unroll
    for (int nb = 0; nb < NB; nb++) {
        float acc = 0.f;
        for (int t = 1 + tid; t < TT; t += 128) {
            const int tg = tb[nb][t];
            const int pr = (t == 1) ? start : tb[nb][t - 1];
            acc += fb[nb][t * LL + tg] + transfer[pr * LL + tg];
        }
        g[nb] = acc;
    }

    // ---- Recurrence state (linear domain, constant rescale) ----
    // W = exp(prev - accumulated 7*ln2); efs pipeline holds exp(f)*2^-7
    // computed two steps ahead of use (MUFU never on the critical path).
    float W[NB], efs0[NB], efs1[NB], fraw[NB];
    {
        const float tstart = transfer[start * LL + jown];
#pragma unroll
        for (int nb = 0; nb < NB; nb++) {
            W[nb]    = __expf(fb[nb][1 * LL + jown] + tstart);  // prev0
            efs0[nb] = __expf(fb[nb][2 * LL + jown]) * C128;
            efs1[nb] = __expf(fb[nb][3 * LL + jown]) * C128;
            fraw[nb] = fb[nb][4 * LL + jown];
        }
    }

    // LDS base (in ulonglong2) of this thread's i-half within a P row
    const int pbase = ih * 17;

    // ---- Main scan: t = 2 .. T-1 (510 iterations) ----
    for (int t = 2; t < TT; t++) {
        const int tn = (t + 3 < TT) ? (t + 3) : (TT - 1);
        const int buf = t & 1;
        float fnew[NB];
#pragma unroll
        for (int nb = 0; nb < NB; nb++) {
            fnew[nb] = fb[nb][tn * LL + jown];          // prefetch 3 ahead
            Psh[buf][nb][fown] = W[nb] * efs0[nb];      // P = exp(prev+f-A)
        }
        __syncthreads();

        // Partial dots over own i-half for both columns, both batches.
        const ulonglong2* P0 =
            reinterpret_cast<const ulonglong2*>(Psh[buf][0]) + pbase;
        const ulonglong2* P1 =
            reinterpret_cast<const ulonglong2*>(Psh[buf][1]) + pbase;
        unsigned long long aA0 = 0ull, bA0 = 0ull, aB0 = 0ull, bB0 = 0ull;
        unsigned long long aA1 = 0ull, bA1 = 0ull, aB1 = 0ull, bB1 = 0ull;
#pragma unroll
        for (int k = 0; k < 16; k++) {
            const unsigned long long ea0 = Ea[2 * k];
            const unsigned long long ea1 = Ea[2 * k + 1];
            const unsigned long long eb0 = Eb[2 * k];
            const unsigned long long eb1 = Eb[2 * k + 1];
            const ulonglong2 q0 = P0[k];
            aA0 = fma2(q0.x, ea0, aA0);
            bA0 = fma2(q0.y, ea1, bA0);
            aB0 = fma2(q0.x, eb0, aB0);
            bB0 = fma2(q0.y, eb1, bB0);
            const ulonglong2 q1 = P1[k];
            aA1 = fma2(q1.x, ea0, aA1);
            bA1 = fma2(q1.y, ea1, bA1);
            aB1 = fma2(q1.x, eb0, aB1);
            bB1 = fma2(q1.y, eb1, bB1);
        }
        float sA0 = hsum2(add2(aA0, bA0));
        float sB0 = hsum2(add2(aB0, bB0));
        float sA1 = hsum2(add2(aA1, bA1));
        float sB1 = hsum2(add2(aB1, bB1));
        sA0 += __shfl_xor_sync(0xffffffffu, sA0, 16);
        sB0 += __shfl_xor_sync(0xffffffffu, sB0, 16);
        sA1 += __shfl_xor_sync(0xffffffffu, sA1, 16);
        sB1 += __shfl_xor_sync(0xffffffffu, sB1, 16);

        W[0] = ih ? sB0 : sA0;   // W_next = S  (rescale already in efs)
        W[1] = ih ? sB1 : sA1;

        // rotate the exp(f)*2^-7 pipeline (MUFU off the critical path)
#pragma unroll
        for (int nb = 0; nb < NB; nb++) {
            efs0[nb] = efs1[nb];
            efs1[nb] = __expf(fraw[nb]) * C128;
            fraw[nb] = fnew[nb];
        }
    }

    // ---- Reconstruct prev once, then epilogue ----
    float prev[NB];
#pragma unroll
    for (int nb = 0; nb < NB; nb++)
        prev[nb] = __logf(W[nb]) + KFINAL;

    const float tstop = transfer[jown * LL + stop];
#pragma unroll
    for (int nb = 0; nb < NB; nb++) {
        const float vv = prev[nb] + tstop;
        float m = vv;
#pragma unroll
        for (int off = 16; off; off >>= 1)
            m = fmaxf(m, __shfl_xor_sync(0xffffffffu, m, off));
        if (lane == 0) smax[nb][wid] = m;
    }
    __syncthreads();
#pragma unroll
    for (int nb = 0; nb < NB; nb++) {
        const float mm = fmaxf(fmaxf(smax[nb][0], smax[nb][1]),
                               fmaxf(smax[nb][2], smax[nb][3]));
        float es = __expf((prev[nb] + tstop) - mm);
        float gg = g[nb];
#pragma unroll
        for (int off = 16; off; off >>= 1) {
            es += __shfl_xor_sync(0xffffffffu, es, off);
            gg += __shfl_xor_sync(0xffffffffu, gg, off);
        }
        if (lane == 0) { ssum[nb][wid] = es; sg[nb][wid] = gg; }
    }
    __syncthreads();

    if (tid < NB) {
        const int nb = tid;
        const float mm = fmaxf(fmaxf(smax[nb][0], smax[nb][1]),
                               fmaxf(smax[nb][2], smax[nb][3]));
        const float Ssum = ssum[nb][0] + ssum[nb][1] + ssum[nb][2] + ssum[nb][3];
        const float sentence = mm + __logf(Ssum);
        const float gsum = sg[nb][0] + sg[nb][1] + sg[nb][2] + sg[nb][3];
        const float emit0 = fb[nb][start];  // feats[b, 0, start]
        out[b0 + nb] = sentence - __expf(emit0 + gsum);
    }
}

extern "C" void kernel_launch(void* const* d_in, const int* in_sizes, int n_in,
                              void* d_out, int out_size) {
    const float* feats    = (const float*)d_in[0];
    const float* transfer = (const float*)d_in[1];
    const int*   target   = (const int*)d_in[2];
    const int*   startp   = (n_in >= 4) ? (const int*)d_in[3] : nullptr;
    const int*   stopp    = (n_in >= 5) ? (const int*)d_in[4] : nullptr;

    crf_kernel<<<NCTA, 128>>>(feats, transfer, target, startp, stopp, (float*)d_out);
}